// round 12
// baseline (speedup 1.0000x reference)
#include <cuda_runtime.h>
#include <cuda_bf16.h>
#include <cstdint>
#include <cstddef>

#define B_   512
#define T_   2048
#define NP   800          // C*M pairs
#define TPB  1024
#define NBLK 128          // B_/4, 4 batches per block

#define L2E     1.4426950408889634f
#define TWO_L2E 2.8853900817779268f

// ---- shared layout (float offsets) ----
#define OFF_SQ   0        // Sq[4 quad][800][4] : S quads transposed, *2*log2e (12800 f)
#define OFF_AT   12800    // float at[16][804]  : A transposed, padded         (12864 f)
#define OFF_UK   25664    // float2 uk[800]     : (2*l2e*U, l2e*(|S|^2+U^2))   ( 1600 f)
#define OFF_W    27264    // float w[4][808]    : stride 808 -> conflict-free  ( 3232 f)
#define OFF_RED  30496    // float red[4][32][16]                              ( 2048 f)
#define OFF_ST   32544    // float st[4][20]                                   (   80 f)
#define OFF_GATE 32624    // float gate[2][4][8]                               (   64 f)
#define OFF_XB   32688    // float xb[2][4]                                    (    8 f)
#define SMEM_FLOATS 32696
#define SMEM_BYTES  (SMEM_FLOATS * 4)

typedef unsigned long long u64;

__device__ float g_gate[(size_t)B_ * T_ * 8];

__device__ __forceinline__ float ex2f(float a)
{
    float r;
    asm("ex2.approx.ftz.f32 %0, %1;" : "=f"(r) : "f"(a));
    return r;
}
__device__ __forceinline__ u64 fma2(u64 b, u64 c, u64 a)   // b*c + a
{
    u64 d;
    asm("fma.rn.f32x2 %0, %1, %2, %3;" : "=l"(d) : "l"(b), "l"(c), "l"(a));
    return d;
}
__device__ __forceinline__ u64 mul2(u64 a, u64 b)
{
    u64 d;
    asm("mul.rn.f32x2 %0, %1, %2;" : "=l"(d) : "l"(a), "l"(b));
    return d;
}
__device__ __forceinline__ float2 upk(u64 a)
{
    float2 f;
    asm("mov.b64 {%0, %1}, %2;" : "=f"(f.x), "=f"(f.y) : "l"(a));
    return f;
}
__device__ __forceinline__ u64 pk2(float lo, float hi)
{
    u64 d;
    asm("mov.b64 %0, {%1, %2};" : "=l"(d) : "f"(lo), "f"(hi));
    return d;
}

// ---------------------------------------------------------------------------
// Kernel 1: gate[b,t,:] = softmax(relu(x*W1+b1) @ W2 + b2). One thread per (b,t).
// ---------------------------------------------------------------------------
__global__ void gate_kernel(const float* __restrict__ x,
                            const float* __restrict__ W1,
                            const float* __restrict__ b1,
                            const float* __restrict__ W2,
                            const float* __restrict__ b2)
{
    int idx = blockIdx.x * blockDim.x + threadIdx.x;
    if (idx >= B_ * T_) return;
    float xv = x[idx];

    float lg[8];
#pragma unroll
    for (int c = 0; c < 8; c++) lg[c] = __ldg(&b2[c]);
#pragma unroll
    for (int jj = 0; jj < 16; jj++) {
        float h = fmaxf(fmaf(xv, __ldg(&W1[jj]), __ldg(&b1[jj])), 0.0f);
#pragma unroll
        for (int c = 0; c < 8; c++)
            lg[c] = fmaf(h, __ldg(&W2[jj * 8 + c]), lg[c]);
    }
    float m = lg[0];
#pragma unroll
    for (int c = 1; c < 8; c++) m = fmaxf(m, lg[c]);
    float e[8], ssum = 0.0f;
#pragma unroll
    for (int c = 0; c < 8; c++) { e[c] = __expf(lg[c] - m); ssum += e[c]; }
    float inv = 1.0f / ssum;
#pragma unroll
    for (int c = 0; c < 8; c++) g_gate[(size_t)idx * 8 + c] = e[c] * inv;
}

// ---------------------------------------------------------------------------
// Kernel 2: recurrent scan. 128 blocks x 1024 threads, 4 batches per block.
// 32 warps/SM (50% occ) for latency hiding. Per-thread work halved vs the
// 512-thread version; A register cache dropped to stay under 64 regs.
// Phase A: (b = tid&3, pp = tid>>2 in 0..255) -> 1-2 dpairs, single 9-fma2
// chain per pair with uk-fold seed. Phase B: (nn = tid&15, j = tid>>4 in
// 0..63) -> 3-4 chunks from smem. Reduction: red[4][32][16], 512-thread final.
// ---------------------------------------------------------------------------
__global__ void __launch_bounds__(TPB, 1)
scan_kernel(const float* __restrict__ x,
            const float* __restrict__ S,
            const float* __restrict__ U,
            const float* __restrict__ A,
            float* __restrict__ out)
{
    extern __shared__ float sm[];
    const int tid = threadIdx.x;
    const int b0  = blockIdx.x * 4;

    // ---------------- stage S', A^T, (u2, k') ----------------
    for (int idx = tid; idx < NP * 16; idx += TPB) {
        int p = idx >> 4, k = idx & 15;
        sm[OFF_SQ + (k >> 2) * 3200 + (p << 2) + (k & 3)] = TWO_L2E * S[idx];
        sm[OFF_AT + k * 804 + p] = A[idx];
    }
    for (int p = tid; p < NP; p += TPB) {
        float acc = 0.0f;
#pragma unroll
        for (int k = 0; k < 16; k++) { float v = S[p * 16 + k]; acc = fmaf(v, v, acc); }
        float uv = U[p];
        sm[OFF_UK + 2 * p]     = TWO_L2E * uv;
        sm[OFF_UK + 2 * p + 1] = L2E * fmaf(uv, uv, acc);
    }
    if (tid < 32) {
        sm[OFF_GATE + tid] = g_gate[((size_t)(b0 + (tid >> 3)) * T_) * 8 + (tid & 7)];
        if (tid < 4) sm[OFF_XB + tid] = x[(size_t)(b0 + tid) * T_];
    }
    __syncthreads();

    const int b    = tid & 3;    // phase A batch
    const int pp   = tid >> 2;   // phase A dpair lane (0..255)
    const int nn   = tid & 15;   // phase B output dim
    const int j    = tid >> 4;   // phase B chunk lane (0..63)
    const int lane = tid & 31;
    const int wrp  = tid >> 5;   // 0..31

    const ulonglong2* Sq2 = (const ulonglong2*)(sm + OFF_SQ);
    const ulonglong2* At2 = (const ulonglong2*)(sm + OFF_AT + nn * 804);
    const ulonglong2* Wb2 = (const ulonglong2*)(sm + OFF_W);

    // packed state (8 x f32x2); xv = raw x_t
    // hs = (-h', 0) seed; xp = (xv, -1) uk-fold multiplier
    u64 s0 = 0, s1 = 0, s2 = 0, s3 = 0, s4 = 0, s5 = 0, s6 = 0, s7 = 0;
    float xv = sm[OFF_XB + b];
    u64 hs = pk2(-L2E * xv * xv, 0.0f);
    u64 xp = pk2(xv, -1.0f);

    for (int t = 0; t < T_; t++) {
        const int par = t & 1;

        // next-step gate/x loads (committed after bar1, consumed at step end)
        float gpre = 0.f, xpre = 0.f;
        const bool pf = (tid < 32) && (t + 1 < T_);
        if (pf) {
            gpre = g_gate[((size_t)(b0 + (tid >> 3)) * T_ + (t + 1)) * 8 + (tid & 7)];
            if (tid < 4) xpre = x[(size_t)(b0 + tid) * T_ + (t + 1)];
        }

        // ---------------- phase A: pairs (2dp, 2dp+1) ----------------
        {
            const float* gsh = sm + OFF_GATE + par * 32 + b * 8;

            auto dpair = [&](int dp, int ci) {
                const int p0 = 2 * dp;
                ulonglong2 q0a = Sq2[p0],        q0b = Sq2[p0 + 1];
                ulonglong2 q1a = Sq2[800 + p0],  q1b = Sq2[801 + p0];
                ulonglong2 q2a = Sq2[1600 + p0], q2b = Sq2[1601 + p0];
                ulonglong2 q3a = Sq2[2400 + p0], q3b = Sq2[2401 + p0];
                ulonglong2 ukp = *(const ulonglong2*)(sm + OFF_UK + 4 * dp);
                float g = gsh[ci];

                u64 da = fma2(ukp.x, xp, hs);     // (u2*xv - h', -k')
                da = fma2(q0a.x, s0, da);
                da = fma2(q0a.y, s1, da);
                da = fma2(q1a.x, s2, da);
                da = fma2(q1a.y, s3, da);
                da = fma2(q2a.x, s4, da);
                da = fma2(q2a.y, s5, da);
                da = fma2(q3a.x, s6, da);
                da = fma2(q3a.y, s7, da);
                float2 fa = upk(da);
                float e0 = fa.x + fa.y;

                u64 db = fma2(ukp.y, xp, hs);
                db = fma2(q0b.x, s0, db);
                db = fma2(q0b.y, s1, db);
                db = fma2(q1b.x, s2, db);
                db = fma2(q1b.y, s3, db);
                db = fma2(q2b.x, s4, db);
                db = fma2(q2b.y, s5, db);
                db = fma2(q3b.x, s6, db);
                db = fma2(q3b.y, s7, db);
                float2 fb = upk(db);
                float e1 = fb.x + fb.y;

                *(float2*)(sm + OFF_W + b * 808 + p0) =
                    make_float2(g * ex2f(e0), g * ex2f(e1));
            };
            dpair(pp, (unsigned)pp / 50u);                       // dp 0..255
            if (pp < 144) {
                int dp = 256 + pp;                                // dp 256..399
                dpair(dp, (unsigned)dp / 50u);
            }
        }
        __syncthreads();                             // bar 1

        // commit prefetched gate/x for t+1
        if (pf) {
            sm[OFF_GATE + (par ^ 1) * 32 + tid] = gpre;
            if (tid < 4) sm[OFF_XB + (par ^ 1) * 4 + tid] = xpre;
        }

        // ---------------- phase B: s_new[b][n] = sum_p w[b][p]*A[p][n] -------
        u64 c0 = 0, c1 = 0, c2 = 0, c3 = 0;
        auto chunkB = [&](int p4) {
            ulonglong2 av = At2[p4];
            ulonglong2 w0 = Wb2[p4];
            ulonglong2 w1 = Wb2[202 + p4];
            ulonglong2 w2 = Wb2[404 + p4];
            ulonglong2 w3 = Wb2[606 + p4];
            c0 = fma2(av.x, w0.x, c0); c0 = fma2(av.y, w0.y, c0);
            c1 = fma2(av.x, w1.x, c1); c1 = fma2(av.y, w1.y, c1);
            c2 = fma2(av.x, w2.x, c2); c2 = fma2(av.y, w2.y, c2);
            c3 = fma2(av.x, w3.x, c3); c3 = fma2(av.y, w3.y, c3);
        };
#pragma unroll
        for (int i = 0; i < 3; i++) chunkB(j + 64 * i);          // chunks 0..191
        if (j < 8) chunkB(192 + j);                               // tail 192..199

        float2 f0 = upk(c0), f1 = upk(c1), f2 = upk(c2), f3 = upk(c3);
        float a0 = f0.x + f0.y, a1 = f1.x + f1.y, a2 = f2.x + f2.y, a3 = f3.x + f3.y;
        a0 += __shfl_xor_sync(0xffffffffu, a0, 16);
        a1 += __shfl_xor_sync(0xffffffffu, a1, 16);
        a2 += __shfl_xor_sync(0xffffffffu, a2, 16);
        a3 += __shfl_xor_sync(0xffffffffu, a3, 16);
        if (lane < 16) {
            sm[OFF_RED +        wrp * 16 + lane] = a0;
            sm[OFF_RED +  512 + wrp * 16 + lane] = a1;
            sm[OFF_RED + 1024 + wrp * 16 + lane] = a2;
            sm[OFF_RED + 1536 + wrp * 16 + lane] = a3;
        }
        __syncthreads();                             // bar 2

        // ---------------- final reduce + output (512 threads, 4+3shfl) -------
        if (tid < 512) {
            const int bb = tid >> 7, n2 = (tid >> 3) & 15, g = tid & 7;
            const float* r = sm + OFF_RED + bb * 512 + n2;
            float v = (r[g * 16] + r[(g + 8) * 16])
                    + (r[(g + 16) * 16] + r[(g + 24) * 16]);
            v += __shfl_xor_sync(0xffffffffu, v, 1);
            v += __shfl_xor_sync(0xffffffffu, v, 2);
            v += __shfl_xor_sync(0xffffffffu, v, 4);
            if (g == 0) {
                sm[OFF_ST + bb * 20 + n2] = v;
                if (n2 == 15) out[(size_t)(b0 + bb) * T_ + t] = v;
            }
        }
        __syncthreads();                             // bar 3

        // reload packed state; recompute h', xp locally
        {
            const ulonglong2* st2 = (const ulonglong2*)(sm + OFF_ST + b * 20);
            ulonglong2 u0 = st2[0], u1 = st2[1], u2 = st2[2], u3 = st2[3];
            s0 = u0.x; s1 = u0.y; s2 = u1.x; s3 = u1.y;
            s4 = u2.x; s5 = u2.y; s6 = u3.x; s7 = u3.y;
            xv = sm[OFF_XB + (par ^ 1) * 4 + b];
            u64 acc = mul2(s0, s0);
            acc = fma2(s1, s1, acc);
            acc = fma2(s2, s2, acc);
            acc = fma2(s3, s3, acc);
            acc = fma2(s4, s4, acc);
            acc = fma2(s5, s5, acc);
            acc = fma2(s6, s6, acc);
            acc = fma2(s7, s7, acc);
            float2 fs = upk(acc);
            float hv = fmaf(xv, xv, fs.x + fs.y);
            hs = pk2(-L2E * hv, 0.0f);
            xp = pk2(xv, -1.0f);
        }
    }
}

// ---------------------------------------------------------------------------
extern "C" void kernel_launch(void* const* d_in, const int* in_sizes, int n_in,
                              void* d_out, int out_size)
{
    const float* x  = (const float*)d_in[0];
    const float* S  = (const float*)d_in[1];
    const float* U  = (const float*)d_in[2];
    const float* A  = (const float*)d_in[3];
    const float* W1 = (const float*)d_in[4];
    const float* b1 = (const float*)d_in[5];
    const float* W2 = (const float*)d_in[6];
    const float* b2 = (const float*)d_in[7];
    float* out = (float*)d_out;

    cudaFuncSetAttribute(scan_kernel,
                         cudaFuncAttributeMaxDynamicSharedMemorySize, SMEM_BYTES);

    gate_kernel<<<(B_ * T_ + 255) / 256, 256>>>(x, W1, b1, W2, b2);
    scan_kernel<<<NBLK, TPB, SMEM_BYTES>>>(x, S, U, A, out);
}